// round 2
// baseline (speedup 1.0000x reference)
#include <cuda_runtime.h>

#define NROWS 131072
#define DD 128
#define RR 5
#define WW 16
#define TILE_N 128
#define NTHR 256
#define KPAN 32
#define PSTRIDE 132          // padded smem row stride (multiple of 4 for float4 alignment)
#define NBLK (NROWS / TILE_N)

// Device-global scratch (allocation-free per harness rules)
__device__ float g_C[RR * DD * DD];
__device__ float g_partial[NBLK];

// ---------------------------------------------------------------------------
// Kernel 1: C_r[d,e] = sum_w ws[w,r] * rel_embeds[w, d*128+e]
// ---------------------------------------------------------------------------
__global__ void build_C_kernel(const float* __restrict__ rel_embeds,
                               const float* __restrict__ ws) {
    int idx = blockIdx.x * blockDim.x + threadIdx.x;
    if (idx >= RR * DD * DD) return;
    int r = idx / (DD * DD);
    int de = idx - r * (DD * DD);
    float acc = 0.f;
#pragma unroll
    for (int w = 0; w < WW; ++w)
        acc = fmaf(ws[w * RR + r], rel_embeds[w * (DD * DD) + de], acc);
    g_C[idx] = acc;
}

// ---------------------------------------------------------------------------
// Kernel 2: per 128-row tile: for r in 0..4:
//   T = E2_tile(128x128) @ C_r^T  (register-blocked fp32 GEMM),
//   logit[n,r] = dot(e1[n,:], T[n,:])  (fused epilogue)
// then softmax(5), preds, per-tile loss partial sum (deterministic).
// ---------------------------------------------------------------------------
__global__ __launch_bounds__(NTHR, 2) void bilinear_kernel(
    const float* __restrict__ e1, const float* __restrict__ e2,
    const int* __restrict__ rels, float* __restrict__ preds_out) {

    __shared__ float sA[KPAN][PSTRIDE];        // E2 panel, k-major: [e][n]
    __shared__ float sB[KPAN][PSTRIDE];        // C_r panel, k-major: [e][d]
    __shared__ float sred[16][TILE_N + 1];     // cross-thread logit reduction
    __shared__ float sloss[TILE_N];

    const int tid = threadIdx.x;
    const int tn  = tid >> 4;    // 0..15: row group (8 rows each)
    const int td  = tid & 15;    // 0..15: col group (8 cols each)
    const int n0  = blockIdx.x * TILE_N;

    float logits[RR];
#pragma unroll
    for (int r = 0; r < RR; ++r) logits[r] = 0.f;

    for (int r = 0; r < RR; ++r) {
        float acc[8][8];
#pragma unroll
        for (int i = 0; i < 8; ++i)
#pragma unroll
            for (int j = 0; j < 8; ++j) acc[i][j] = 0.f;

        const float4* __restrict__ e2v = reinterpret_cast<const float4*>(e2 + (size_t)n0 * DD);
        const float4* __restrict__ cv  = reinterpret_cast<const float4*>(g_C + (size_t)r * DD * DD);

        for (int p0 = 0; p0 < DD; p0 += KPAN) {
            const int pq = p0 >> 2;  // float4 offset within a 128-float row
            // Load panels transposed into smem.
            // f in [0,1024): each covers one float4. Lane mapping keeps LDG
            // 64B-coalesced (4 eq per 8 rows) and STS at worst 2-way conflicted.
#pragma unroll
            for (int s = 0; s < 4; ++s) {
                int f  = tid + s * NTHR;                 // 0..1023
                int eq = (f & 3) + ((f >> 9) << 2);      // 0..7 (which float4 in the 32-e panel)
                int n  = (f >> 2) & 127;                 // 0..127 (row)
                float4 va = e2v[n * 32 + pq + eq];
                float4 vb = cv [n * 32 + pq + eq];
                int e = eq * 4;
                sA[e + 0][n] = va.x; sA[e + 1][n] = va.y;
                sA[e + 2][n] = va.z; sA[e + 3][n] = va.w;
                sB[e + 0][n] = vb.x; sB[e + 1][n] = vb.y;
                sB[e + 2][n] = vb.z; sB[e + 3][n] = vb.w;
            }
            __syncthreads();

#pragma unroll
            for (int k = 0; k < KPAN; ++k) {
                float a[8], b[8];
                *(float4*)&a[0] = *(const float4*)&sA[k][tn * 8];
                *(float4*)&a[4] = *(const float4*)&sA[k][tn * 8 + 4];
                *(float4*)&b[0] = *(const float4*)&sB[k][td * 8];
                *(float4*)&b[4] = *(const float4*)&sB[k][td * 8 + 4];
#pragma unroll
                for (int i = 0; i < 8; ++i)
#pragma unroll
                    for (int j = 0; j < 8; ++j)
                        acc[i][j] = fmaf(a[i], b[j], acc[i][j]);
            }
            __syncthreads();
        }

        // Fused epilogue: partial[n] = sum_j T[n, d_j] * e1[n, d_j]  (fp32 exact)
#pragma unroll
        for (int i = 0; i < 8; ++i) {
            int rowl = tn * 8 + i;
            const float4* e1r = reinterpret_cast<const float4*>(
                e1 + (size_t)(n0 + rowl) * DD + td * 8);
            float4 u0 = e1r[0];
            float4 u1 = e1r[1];
            float p = acc[i][0]*u0.x + acc[i][1]*u0.y + acc[i][2]*u0.z + acc[i][3]*u0.w
                    + acc[i][4]*u1.x + acc[i][5]*u1.y + acc[i][6]*u1.z + acc[i][7]*u1.w;
            sred[td][rowl] = p;
        }
        __syncthreads();
        if (tid < TILE_N) {
            float s = 0.f;
#pragma unroll
            for (int g = 0; g < 16; ++g) s += sred[g][tid];
            logits[r] = s;
        }
        __syncthreads();
    }

    // Softmax(5) + preds + loss contribution
    float lossval = 0.f;
    if (tid < TILE_N) {
        int row = n0 + tid;
        float m = logits[0];
#pragma unroll
        for (int j = 1; j < RR; ++j) m = fmaxf(m, logits[j]);
        float se = 0.f, pe = 0.f;
#pragma unroll
        for (int j = 0; j < RR; ++j) {
            float ex = expf(logits[j] - m);
            se += ex;
            pe += (float)(j + 1) * ex;
        }
        preds_out[row] = pe / se;
        int lab = rels[row];
        float ll = logits[0];
#pragma unroll
        for (int j = 1; j < RR; ++j) ll = (lab == j) ? logits[j] : ll;
        lossval = -(ll - m - logf(se));
    }
    if (tid < TILE_N) sloss[tid] = lossval;
    __syncthreads();
#pragma unroll
    for (int off = TILE_N / 2; off > 0; off >>= 1) {
        if (tid < off) sloss[tid] += sloss[tid + off];
        __syncthreads();
    }
    if (tid == 0) g_partial[blockIdx.x] = sloss[0];
}

// ---------------------------------------------------------------------------
// Kernel 3: deterministic fixed-order reduction of per-tile loss partials
// ---------------------------------------------------------------------------
__global__ void finalize_kernel(float* __restrict__ out, int has_loss) {
    __shared__ float s[256];
    int tid = threadIdx.x;
    float v = 0.f;
    for (int i = tid; i < NBLK; i += 256) v += g_partial[i];
    s[tid] = v;
    __syncthreads();
#pragma unroll
    for (int off = 128; off > 0; off >>= 1) {
        if (tid < off) s[tid] += s[tid + off];
        __syncthreads();
    }
    if (tid == 0 && has_loss) out[0] = s[0] / (float)NROWS;
}

// ---------------------------------------------------------------------------
extern "C" void kernel_launch(void* const* d_in, const int* in_sizes, int n_in,
                              void* d_out, int out_size) {
    const float* e1         = (const float*)d_in[0];
    const float* e2         = (const float*)d_in[1];
    const float* rel_embeds = (const float*)d_in[2];
    const float* ws         = (const float*)d_in[3];
    const int*   rels       = (const int*)d_in[4];   // jax int64 request -> int32 (x64 disabled)
    float* out = (float*)d_out;

    int loss_off = out_size - NROWS;   // expected 1: [loss, preds(N)]
    if (loss_off < 0) loss_off = 0;
    float* preds = out + loss_off;

    build_C_kernel<<<(RR * DD * DD + 255) / 256, 256>>>(rel_embeds, ws);
    bilinear_kernel<<<NBLK, NTHR>>>(e1, e2, rels, preds);
    finalize_kernel<<<1, 256>>>(out, loss_off > 0 ? 1 : 0);
}

// round 4
// speedup vs baseline: 2.2295x; 2.2295x over previous
#include <cuda_runtime.h>
#include <cuda_bf16.h>
#include <stdint.h>

#define NROWS 131072
#define DD    128
#define RR    5
#define WW    16
#define TILE  128
#define NBLK  (NROWS/TILE)
#define NTHR  256

// bf16 element strides (padded: +8 bf16 = 16B per row -> conflict-free ldmatrix)
#define SAS 136
#define SBS 136
#define E1S 132   // float stride for e1 tile

// dynamic smem layout (bytes)
#define SM_A0   0
#define SM_A1   34816
#define SM_B    69632
#define SM_BSZ  34816
#define SM_E1   139264
#define SM_LOG  206848
#define SM_LOSS 211968
#define SM_TOTAL 212480

__device__ __align__(256) __nv_bfloat16 g_B[2 * RR * DD * DD];  // [split][r][e][d]
__device__ float g_partial[NBLK];

// ---------------------------------------------------------------------------
__device__ __forceinline__ uint32_t smem_u32(const void* p) {
    uint32_t a;
    asm("{ .reg .u64 t; cvta.to.shared.u64 t, %1; cvt.u32.u64 %0, t; }" : "=r"(a) : "l"(p));
    return a;
}
__device__ __forceinline__ void cp16(uint32_t dst, const void* src) {
    asm volatile("cp.async.cg.shared.global [%0], [%1], 16;" :: "r"(dst), "l"(src));
}
#define CP_COMMIT() asm volatile("cp.async.commit_group;" ::: "memory")
#define CP_WAIT(N)  asm volatile("cp.async.wait_group %0;" :: "n"(N) : "memory")

#define LDSM_X4(R, ADDR) \
    asm volatile("ldmatrix.sync.aligned.m8n8.x4.shared.b16 {%0,%1,%2,%3}, [%4];" \
        : "=r"((R)[0]), "=r"((R)[1]), "=r"((R)[2]), "=r"((R)[3]) : "r"(ADDR))
#define LDSM_X4T(R, ADDR) \
    asm volatile("ldmatrix.sync.aligned.m8n8.x4.trans.shared.b16 {%0,%1,%2,%3}, [%4];" \
        : "=r"((R)[0]), "=r"((R)[1]), "=r"((R)[2]), "=r"((R)[3]) : "r"(ADDR))

#define MMA16816(D, A, B0, B1) \
    asm volatile("mma.sync.aligned.m16n8k16.row.col.f32.bf16.bf16.f32 " \
        "{%0,%1,%2,%3},{%4,%5,%6,%7},{%8,%9},{%0,%1,%2,%3};" \
        : "+f"((D)[0]), "+f"((D)[1]), "+f"((D)[2]), "+f"((D)[3]) \
        : "r"((A)[0]), "r"((A)[1]), "r"((A)[2]), "r"((A)[3]), "r"(B0), "r"(B1))

__device__ __forceinline__ uint32_t pack_bf16(float x, float y) {
    __nv_bfloat16 hx = __float2bfloat16(x), hy = __float2bfloat16(y);
    return (uint32_t)__bfloat16_as_ushort(hx) | ((uint32_t)__bfloat16_as_ushort(hy) << 16);
}

// ---------------------------------------------------------------------------
// prep: C_r[d][e] = sum_w ws[w,r]*rel[w][d][e]; 2-way bf16 split;
// store transposed [r][e][d] so smem B rows are k(e)-major for ldmatrix.trans.
// ---------------------------------------------------------------------------
__global__ void prep_kernel(const float* __restrict__ rel, const float* __restrict__ ws) {
    int idx = blockIdx.x * blockDim.x + threadIdx.x;
    if (idx >= RR * DD * DD) return;
    int r = idx / (DD * DD);
    int rem = idx - r * (DD * DD);
    int d = rem >> 7;
    int e = rem & 127;
    float c = 0.f;
#pragma unroll
    for (int w = 0; w < WW; ++w)
        c = fmaf(ws[w * RR + r], rel[w * DD * DD + d * DD + e], c);
    __nv_bfloat16 b0 = __float2bfloat16(c);
    __nv_bfloat16 b1 = __float2bfloat16(c - __bfloat162float(b0));
    g_B[((size_t)r * DD + e) * DD + d]        = b0;
    g_B[((size_t)(RR + r) * DD + e) * DD + d] = b1;
}

// ---------------------------------------------------------------------------
__device__ __forceinline__ void load_B_stage(uint32_t sb, int tid, int st) {
    int r = st >> 1, ph = st & 1, buf = st & 1;
    const char* src = (const char*)g_B + (size_t)(ph * RR + r) * DD * DD * 2;
    uint32_t dbase = sb + SM_B + buf * SM_BSZ;
#pragma unroll
    for (int j = 0; j < 8; ++j) {
        int i = tid + j * NTHR;          // 0..2047 16B chunks
        int e = i >> 4, c = i & 15;
        cp16(dbase + e * (SBS * 2) + c * 16, src + e * 256 + c * 16);
    }
}

__global__ __launch_bounds__(NTHR, 1) void bilinear_mma_kernel(
    const float* __restrict__ e1g, const float* __restrict__ e2g,
    const int* __restrict__ rels, float* __restrict__ preds) {

    extern __shared__ char smem[];
    const uint32_t sb = smem_u32(smem);
    const int tid  = threadIdx.x;
    const int lane = tid & 31;
    const int wid  = tid >> 5;
    const int n0   = blockIdx.x * TILE;

    // prefetch B stage 0
    load_B_stage(sb, tid, 0);
    CP_COMMIT();

    // fill A0/A1 (2-way bf16 split of E2 tile) and e1 (fp32) into smem
    {
        const float4* e2v = (const float4*)(e2g + (size_t)n0 * DD);
        const float4* e1v = (const float4*)(e1g + (size_t)n0 * DD);
        float* se1 = (float*)(smem + SM_E1);
#pragma unroll
        for (int j = 0; j < 16; ++j) {
            int i = tid + j * NTHR;      // 0..4095
            int n = i >> 5, q = i & 31;
            float4 t = e2v[n * 32 + q];
            int k = q * 4;
            uint32_t lo0 = pack_bf16(t.x, t.y);
            uint32_t hi0 = pack_bf16(t.z, t.w);
            float rx = t.x - __bfloat162float(__float2bfloat16(t.x));
            float ry = t.y - __bfloat162float(__float2bfloat16(t.y));
            float rz = t.z - __bfloat162float(__float2bfloat16(t.z));
            float rw = t.w - __bfloat162float(__float2bfloat16(t.w));
            uint32_t lo1 = pack_bf16(rx, ry);
            uint32_t hi1 = pack_bf16(rz, rw);
            uint32_t aoff = (uint32_t)(n * SAS + k) * 2;
            *(uint32_t*)(smem + SM_A0 + aoff)     = lo0;
            *(uint32_t*)(smem + SM_A0 + aoff + 4) = hi0;
            *(uint32_t*)(smem + SM_A1 + aoff)     = lo1;
            *(uint32_t*)(smem + SM_A1 + aoff + 4) = hi1;
            float4 u = e1v[n * 32 + q];
            se1[n * E1S + k + 0] = u.x;
            se1[n * E1S + k + 1] = u.y;
            se1[n * E1S + k + 2] = u.z;
            se1[n * E1S + k + 3] = u.w;
        }
    }
    __syncthreads();   // A/e1 ready; also all warps past "previous" stage trivially

    // warp tile: rows [(wid>>1)*32, +32), cols [(wid&1)*64, +64)
    const int rowbase = (wid >> 1) * 32;
    const int chalf   = (wid & 1) * 64;
    const uint32_t aR = rowbase + (lane & 15);
    const uint32_t aC = (lane >> 4) * 8;
    const uint32_t addrA0 = sb + SM_A0 + (aR * SAS + aC) * 2;
    const uint32_t addrA1 = sb + SM_A1 + (aR * SAS + aC) * 2;
    const uint32_t bR = lane & 15;
    const uint32_t bC = chalf + (lane >> 4) * 8;
    const uint32_t addrBb = sb + SM_B + (bR * SBS + bC) * 2;

    float acc[2][8][4];
#pragma unroll
    for (int mb = 0; mb < 2; ++mb)
#pragma unroll
        for (int n8 = 0; n8 < 8; ++n8)
#pragma unroll
            for (int q = 0; q < 4; ++q) acc[mb][n8][q] = 0.f;

    float* slog = (float*)(smem + SM_LOG);
    const float* se1 = (const float*)(smem + SM_E1);

    for (int st = 0; st < 10; ++st) {
        if (st < 9) {
            load_B_stage(sb, tid, st + 1);   // safe: bottom sync of st-1 passed
            CP_COMMIT();
            CP_WAIT(1);                      // stage st's group complete
        } else {
            CP_WAIT(0);
        }
        __syncthreads();

        const uint32_t bbuf = addrBb + (uint32_t)(st & 1) * SM_BSZ;

        if ((st & 1) == 0) {
            // sweep1: acc += A0*B0 + A1*B0
#pragma unroll
            for (int ks = 0; ks < 8; ++ks) {
                uint32_t a0f[2][4], a1f[2][4], bf[4][4];
#pragma unroll
                for (int mb = 0; mb < 2; ++mb) {
                    LDSM_X4(a0f[mb], addrA0 + (uint32_t)(mb * 16 * SAS + ks * 16) * 2);
                    LDSM_X4(a1f[mb], addrA1 + (uint32_t)(mb * 16 * SAS + ks * 16) * 2);
                }
#pragma unroll
                for (int nb = 0; nb < 4; ++nb)
                    LDSM_X4T(bf[nb], bbuf + (uint32_t)(ks * 16 * SBS + nb * 16) * 2);
#pragma unroll
                for (int mb = 0; mb < 2; ++mb)
#pragma unroll
                    for (int n8 = 0; n8 < 8; ++n8) {
                        const int nb = n8 >> 1, h = (n8 & 1) * 2;
                        MMA16816(acc[mb][n8], a0f[mb], bf[nb][h], bf[nb][h + 1]);
                        MMA16816(acc[mb][n8], a1f[mb], bf[nb][h], bf[nb][h + 1]);
                    }
            }
        } else {
            // sweep2: acc += A0*B1
#pragma unroll
            for (int ks = 0; ks < 8; ++ks) {
                uint32_t a0f[2][4], bf[4][4];
#pragma unroll
                for (int mb = 0; mb < 2; ++mb)
                    LDSM_X4(a0f[mb], addrA0 + (uint32_t)(mb * 16 * SAS + ks * 16) * 2);
#pragma unroll
                for (int nb = 0; nb < 4; ++nb)
                    LDSM_X4T(bf[nb], bbuf + (uint32_t)(ks * 16 * SBS + nb * 16) * 2);
#pragma unroll
                for (int mb = 0; mb < 2; ++mb)
#pragma unroll
                    for (int n8 = 0; n8 < 8; ++n8) {
                        const int nb = n8 >> 1, h = (n8 & 1) * 2;
                        MMA16816(acc[mb][n8], a0f[mb], bf[nb][h], bf[nb][h + 1]);
                    }
            }
            // epilogue for r = st>>1: logit partial = dot(acc row, e1 row)
            const int r = st >> 1;
#pragma unroll
            for (int mb = 0; mb < 2; ++mb)
#pragma unroll
                for (int rs = 0; rs < 2; ++rs) {
                    const int row = rowbase + mb * 16 + rs * 8 + (lane >> 2);
                    const float* er = se1 + row * E1S + chalf + (lane & 3) * 2;
                    float s = 0.f;
#pragma unroll
                    for (int n8 = 0; n8 < 8; ++n8) {
                        float2 u = *(const float2*)(er + n8 * 8);
                        s = fmaf(acc[mb][n8][rs * 2 + 0], u.x, s);
                        s = fmaf(acc[mb][n8][rs * 2 + 1], u.y, s);
                        acc[mb][n8][rs * 2 + 0] = 0.f;
                        acc[mb][n8][rs * 2 + 1] = 0.f;
                    }
                    s += __shfl_xor_sync(0xffffffffu, s, 1);
                    s += __shfl_xor_sync(0xffffffffu, s, 2);
                    if ((lane & 3) == 0)
                        slog[(r * 2 + (wid & 1)) * TILE + row] = s;
                }
        }
        __syncthreads();   // protects buffer (st&1) from overwrite at st+1's prefetch
    }

    // --- softmax(5), preds, loss -------------------------------------------
    float* slossp = (float*)(smem + SM_LOSS);
    if (tid < TILE) {
        const int row = n0 + tid;
        float lg[RR];
#pragma unroll
        for (int r = 0; r < RR; ++r)
            lg[r] = slog[(r * 2 + 0) * TILE + tid] + slog[(r * 2 + 1) * TILE + tid];
        float m = lg[0];
#pragma unroll
        for (int j = 1; j < RR; ++j) m = fmaxf(m, lg[j]);
        float se = 0.f, pe = 0.f;
#pragma unroll
        for (int j = 0; j < RR; ++j) {
            float ex = expf(lg[j] - m);
            se += ex;
            pe += (float)(j + 1) * ex;
        }
        preds[row] = pe / se;
        int lab = rels[row];
        float ll = lg[0];
#pragma unroll
        for (int j = 1; j < RR; ++j) ll = (lab == j) ? lg[j] : ll;
        slossp[tid] = -(ll - m - logf(se));
    }
    __syncthreads();
#pragma unroll
    for (int off = 64; off > 0; off >>= 1) {
        if (tid < off) slossp[tid] += slossp[tid + off];
        __syncthreads();
    }
    if (tid == 0) g_partial[blockIdx.x] = slossp[0];
}

// ---------------------------------------------------------------------------
__global__ void finalize_kernel(float* __restrict__ out, int has_loss) {
    __shared__ float s[256];
    int tid = threadIdx.x;
    float v = 0.f;
    for (int i = tid; i < NBLK; i += 256) v += g_partial[i];
    s[tid] = v;
    __syncthreads();
#pragma unroll
    for (int off = 128; off > 0; off >>= 1) {
        if (tid < off) s[tid] += s[tid + off];
        __syncthreads();
    }
    if (tid == 0 && has_loss) out[0] = s[0] / (float)NROWS;
}

// ---------------------------------------------------------------------------
extern "C" void kernel_launch(void* const* d_in, const int* in_sizes, int n_in,
                              void* d_out, int out_size) {
    const float* e1         = (const float*)d_in[0];
    const float* e2         = (const float*)d_in[1];
    const float* rel_embeds = (const float*)d_in[2];
    const float* ws         = (const float*)d_in[3];
    const int*   rels       = (const int*)d_in[4];
    float* out = (float*)d_out;

    int loss_off = out_size - NROWS;
    if (loss_off < 0) loss_off = 0;
    float* preds = out + loss_off;

    static int configured = 0;
    cudaFuncSetAttribute(bilinear_mma_kernel,
                         cudaFuncAttributeMaxDynamicSharedMemorySize, SM_TOTAL);
    (void)configured;

    prep_kernel<<<(RR * DD * DD + 255) / 256, 256>>>(rel_embeds, ws);
    bilinear_mma_kernel<<<NBLK, NTHR, SM_TOTAL>>>(e1, e2, rels, preds);
    finalize_kernel<<<1, 256>>>(out, loss_off > 0 ? 1 : 0);
}